// round 2
// baseline (speedup 1.0000x reference)
#include <cuda_runtime.h>

#define NPED 4096

// constants
#define DT        0.4f
#define K_ATTR    2.0f
#define PED_SPEED 1.0f
#define INV_MASS  (1.0f/60.0f)
#define EPS       1e-8f
#define A_COST    5.0f
#define B_COST    2.0f
// exp fold: 10*exp((0.6-dist)/0.71) = exp2( C1 - dist*C2 )
// C2 = (1/0.71)*log2(e);  C1 = (0.6/0.71)*log2(e) + log2(10)
#define C2_EXP 2.0319648f      /* 1.4084507 * 1.4426950 */
#define C1_EXP 4.5411053f      /* 0.8450704 * 1.4426950 + 3.3219281 */

__device__ __forceinline__ float ex2_approx(float x) {
    float r; asm("ex2.approx.f32 %0, %1;" : "=f"(r) : "f"(x)); return r;
}
__device__ __forceinline__ float rsqrt_approx(float x) {
    float r; asm("rsqrt.approx.f32 %0, %1;" : "=f"(r) : "f"(x)); return r;
}

// Kernel 1: forces + propagation. One warp per pedestrian i.
__global__ void __launch_bounds__(256) forces_prop_kernel(
    const float* __restrict__ state,   // [N,4]
    const float* __restrict__ goal,    // [N,2]
    float* __restrict__ out_state)     // [N,4]
{
    int warp = (blockIdx.x * blockDim.x + threadIdx.x) >> 5;
    int lane = threadIdx.x & 31;
    if (warp >= NPED) return;
    const int i = warp;

    const float xi = state[i*4 + 0];
    const float yi = state[i*4 + 1];

    float fx = 0.0f, fy = 0.0f;
    const float2* __restrict__ pos2 = (const float2*)state; // row = 2 float2: pos, vel

    #pragma unroll 4
    for (int j = lane; j < NPED; j += 32) {
        float2 pj = pos2[j*2];           // position of j
        float dx = xi - pj.x;
        float dy = yi - pj.y;
        float d2 = fmaf(dx, dx, fmaf(dy, dy, EPS));
        float rd = rsqrt_approx(d2);
        float dist = d2 * rd;                              // = sqrt(d2)
        float coef = ex2_approx(fmaf(dist, -C2_EXP, C1_EXP)) * rd; // mag/dist (ALPHA folded)
        // j == i: dx = dy = 0 exactly -> contribution exactly 0, no mask needed
        fx = fmaf(coef, dx, fx);
        fy = fmaf(coef, dy, fy);
    }
    // warp reduction
    #pragma unroll
    for (int o = 16; o > 0; o >>= 1) {
        fx += __shfl_xor_sync(0xffffffffu, fx, o);
        fy += __shfl_xor_sync(0xffffffffu, fy, o);
    }

    if (lane == 0) {
        float vx = state[i*4 + 2];
        float vy = state[i*4 + 3];
        float gx = goal[i*2 + 0];
        float gy = goal[i*2 + 1];

        float tgx = gx - xi, tgy = gy - yi;
        float dg2 = fmaf(tgx, tgx, fmaf(tgy, tgy, EPS));
        float rdg = rsqrt_approx(dg2);
        float afx = K_ATTR * fmaf(PED_SPEED * tgx, rdg, -vx);
        float afy = K_ATTR * fmaf(PED_SPEED * tgy, rdg, -vy);

        float Fx = fmaf(fx, INV_MASS, afx);
        float Fy = fmaf(fy, INV_MASS, afy);

        float npx = xi + vx * DT + 0.5f * Fx * (DT * DT);
        float npy = yi + vy * DT + 0.5f * Fy * (DT * DT);
        float nvx = fmaf(Fx, DT, vx);
        float nvy = fmaf(Fy, DT, vy);
        float spd2 = fmaf(nvx, nvx, fmaf(nvy, nvy, EPS));
        float spd  = sqrtf(spd2);
        float scale = fminf(1.0f, PED_SPEED / spd);

        out_state[i*4 + 0] = npx;
        out_state[i*4 + 1] = npy;
        out_state[i*4 + 2] = nvx * scale;
        out_state[i*4 + 3] = nvy * scale;
    }
}

// Kernel 2: cost reduction (single block)
__global__ void __launch_bounds__(1024) cost_kernel(
    const float* __restrict__ state,      // input state [N,4]
    const float* __restrict__ goal,       // [N,2]
    const float* __restrict__ observed,   // [N,4]
    const float* __restrict__ cost_in,    // [1]
    const float* __restrict__ out_state,  // [N,4] (new state)
    float* __restrict__ cost_out)         // [1]
{
    __shared__ float s_dev[1024];
    __shared__ float s_blm[1024];
    const int tid = threadIdx.x;

    const float rx = out_state[0];
    const float ry = out_state[1];

    float dev = 0.0f, blm = 0.0f;
    for (int p = 1 + tid; p < NPED; p += 1024) {
        float px = out_state[p*4 + 0];
        float py = out_state[p*4 + 1];
        float ox = observed[p*4 + 0];
        float oy = observed[p*4 + 1];
        float ddx = px - ox, ddy = py - oy;
        dev += sqrtf(fmaf(ddx, ddx, fmaf(ddy, ddy, EPS)));
        float bx = px - rx, by = py - ry;
        float d = sqrtf(fmaf(bx, bx, fmaf(by, by, EPS)));
        blm += __expf(-d);   // E_COST = 1
    }
    s_dev[tid] = dev;
    s_blm[tid] = blm;
    __syncthreads();
    for (int s = 512; s > 0; s >>= 1) {
        if (tid < s) {
            s_dev[tid] += s_dev[tid + s];
            s_blm[tid] += s_blm[tid + s];
        }
        __syncthreads();
    }
    if (tid == 0) {
        float ix = state[0], iy = state[1];
        float gx = goal[0],  gy = goal[1];
        float d1x = ix - gx, d1y = iy - gy;
        float d2x = rx - gx, d2y = ry - gy;
        float pg = sqrtf(fmaf(d1x, d1x, fmaf(d1y, d1y, EPS)))
                 - sqrtf(fmaf(d2x, d2x, fmaf(d2y, d2y, EPS)));
        cost_out[0] = cost_in[0] + A_COST * s_dev[0] + B_COST * s_blm[0] - pg;
    }
}

// Kernel 3: stacked = concat(stacked_in, state). Scalar copies (dest is
// 4-byte aligned only: stacked region starts at float offset N*4+1).
__global__ void __launch_bounds__(256) stack_kernel(
    const float* __restrict__ stacked_in,  // [N*4]
    const float* __restrict__ state,       // [N*4]
    float* __restrict__ out_stacked)       // [2*N*4]
{
    int idx = blockIdx.x * blockDim.x + threadIdx.x;
    if (idx < NPED * 4) {
        out_stacked[idx]            = stacked_in[idx];
        out_stacked[NPED*4 + idx]   = state[idx];
    }
}

extern "C" void kernel_launch(void* const* d_in, const int* in_sizes, int n_in,
                              void* d_out, int out_size) {
    const float* state      = (const float*)d_in[0];   // [N,4]
    const float* cost_in    = (const float*)d_in[1];   // [1]
    const float* stacked_in = (const float*)d_in[2];   // [N,4]
    const float* goal       = (const float*)d_in[3];   // [N,2]
    const float* observed   = (const float*)d_in[4];   // [N,4]

    float* out = (float*)d_out;
    float* out_state   = out;                 // N*4
    float* out_cost    = out + NPED*4;        // 1
    float* out_stacked = out + NPED*4 + 1;    // 2*N*4

    // independent copy first
    stack_kernel<<<(NPED*4 + 255) / 256, 256>>>(stacked_in, state, out_stacked);

    // forces + propagation: one warp per pedestrian -> 4096 warps
    forces_prop_kernel<<<(NPED * 32) / 256, 256>>>(state, goal, out_state);

    // cost (depends on out_state)
    cost_kernel<<<1, 1024>>>(state, goal, observed, cost_in, out_state, out_cost);
}

// round 4
// speedup vs baseline: 1.0743x; 1.0743x over previous
#include <cuda_runtime.h>

#define NPED 4096
#define TILE 2048          // float2 per smem tile (16KB), 2 tiles cover N

#define DT        0.4f
#define K_ATTR    2.0f
#define PED_SPEED 1.0f
#define INV_MASS  (1.0f/60.0f)
#define EPS       1e-8f
#define A_COST    5.0f
#define B_COST    2.0f
// 10*exp((0.6-dist)/0.71) = exp2(C1 - dist*C2)
#define C2_EXP 2.0319648f
#define C1_EXP 4.5411053f

__device__ __forceinline__ float ex2_approx(float x) {
    float r; asm("ex2.approx.f32 %0, %1;" : "=f"(r) : "f"(x)); return r;
}
__device__ __forceinline__ float rsqrt_approx(float x) {
    float r; asm("rsqrt.approx.f32 %0, %1;" : "=f"(r) : "f"(x)); return r;
}

// Kernel A: stacked-copy + forces + propagation.
// 512 blocks x 256 threads; warp w of block b owns pedestrian i = b*8+w.
// j-loop reads packed positions from shared-memory tiles.
__global__ void __launch_bounds__(256) forces_prop_stack_kernel(
    const float* __restrict__ state,       // [N,4]
    const float* __restrict__ goal,        // [N,2]
    const float* __restrict__ stacked_in,  // [N*4]
    float* __restrict__ out_state,         // [N,4]
    float* __restrict__ out_stacked)       // [2*N*4] (4B-aligned only)
{
    __shared__ float2 spos[TILE];

    const int tid  = threadIdx.x;
    const int lane = tid & 31;
    const int i    = blockIdx.x * 8 + (tid >> 5);

    // fused concat copy: first 64 blocks cover 16384 floats each side
    {
        int g = blockIdx.x * 256 + tid;
        if (g < NPED * 4) {
            out_stacked[g]            = stacked_in[g];
            out_stacked[NPED * 4 + g] = state[g];
        }
    }

    const float xi = state[i*4 + 0];
    const float yi = state[i*4 + 1];

    float fx = 0.0f, fy = 0.0f;

    const float2* __restrict__ pos2 = (const float2*)state;  // row = {pos, vel}

    #pragma unroll
    for (int t = 0; t < NPED / TILE; t++) {
        // cooperative packed load of tile t
        #pragma unroll
        for (int k = tid; k < TILE; k += 256)
            spos[k] = pos2[(t * TILE + k) * 2];
        __syncthreads();

        #pragma unroll 4
        for (int jj = lane; jj < TILE; jj += 32) {
            float2 pj = spos[jj];
            float dx = xi - pj.x;
            float dy = yi - pj.y;
            float d2 = fmaf(dx, dx, fmaf(dy, dy, EPS));
            float rd = rsqrt_approx(d2);
            float dist = d2 * rd;                                   // sqrt(d2)
            float coef = ex2_approx(fmaf(dist, -C2_EXP, C1_EXP)) * rd;
            // j==i: dx=dy=0 exactly -> contributes exactly 0
            fx = fmaf(coef, dx, fx);
            fy = fmaf(coef, dy, fy);
        }
        __syncthreads();
    }

    // warp reduction
    #pragma unroll
    for (int o = 16; o > 0; o >>= 1) {
        fx += __shfl_xor_sync(0xffffffffu, fx, o);
        fy += __shfl_xor_sync(0xffffffffu, fy, o);
    }

    if (lane == 0) {
        float vx = state[i*4 + 2];
        float vy = state[i*4 + 3];
        float gx = goal[i*2 + 0];
        float gy = goal[i*2 + 1];

        float tgx = gx - xi, tgy = gy - yi;
        float dg2 = fmaf(tgx, tgx, fmaf(tgy, tgy, EPS));
        float rdg = rsqrt_approx(dg2);
        float afx = K_ATTR * fmaf(PED_SPEED * tgx, rdg, -vx);
        float afy = K_ATTR * fmaf(PED_SPEED * tgy, rdg, -vy);

        float Fx = fmaf(fx, INV_MASS, afx);
        float Fy = fmaf(fy, INV_MASS, afy);

        float npx = xi + vx * DT + 0.5f * Fx * (DT * DT);
        float npy = yi + vy * DT + 0.5f * Fy * (DT * DT);
        float nvx = fmaf(Fx, DT, vx);
        float nvy = fmaf(Fy, DT, vy);
        float spd = sqrtf(fmaf(nvx, nvx, fmaf(nvy, nvy, EPS)));
        float scale = fminf(1.0f, PED_SPEED / spd);

        out_state[i*4 + 0] = npx;
        out_state[i*4 + 1] = npy;
        out_state[i*4 + 2] = nvx * scale;
        out_state[i*4 + 3] = nvy * scale;
    }
}

// Kernel B: cost reduction (single block, 1024 threads, shuffle+smem)
__global__ void __launch_bounds__(1024) cost_kernel(
    const float* __restrict__ state,
    const float* __restrict__ goal,
    const float* __restrict__ observed,
    const float* __restrict__ cost_in,
    const float* __restrict__ out_state,
    float* __restrict__ cost_out)
{
    __shared__ float s_dev[32];
    __shared__ float s_blm[32];
    const int tid = threadIdx.x;

    const float rx = out_state[0];
    const float ry = out_state[1];

    float dev = 0.0f, blm = 0.0f;
    #pragma unroll
    for (int p = 1 + tid; p < NPED; p += 1024) {
        float px = out_state[p*4 + 0];
        float py = out_state[p*4 + 1];
        float ox = observed[p*4 + 0];
        float oy = observed[p*4 + 1];
        float ddx = px - ox, ddy = py - oy;
        dev += sqrtf(fmaf(ddx, ddx, fmaf(ddy, ddy, EPS)));
        float bx = px - rx, by = py - ry;
        float d = sqrtf(fmaf(bx, bx, fmaf(by, by, EPS)));
        blm += __expf(-d);
    }
    #pragma unroll
    for (int o = 16; o > 0; o >>= 1) {
        dev += __shfl_xor_sync(0xffffffffu, dev, o);
        blm += __shfl_xor_sync(0xffffffffu, blm, o);
    }
    if ((tid & 31) == 0) { s_dev[tid >> 5] = dev; s_blm[tid >> 5] = blm; }
    __syncthreads();
    if (tid < 32) {
        dev = s_dev[tid];
        blm = s_blm[tid];
        #pragma unroll
        for (int o = 16; o > 0; o >>= 1) {
            dev += __shfl_xor_sync(0xffffffffu, dev, o);
            blm += __shfl_xor_sync(0xffffffffu, blm, o);
        }
        if (tid == 0) {
            float ix = state[0], iy = state[1];
            float gx = goal[0],  gy = goal[1];
            float d1x = ix - gx, d1y = iy - gy;
            float d2x = rx - gx, d2y = ry - gy;
            float pg = sqrtf(fmaf(d1x, d1x, fmaf(d1y, d1y, EPS)))
                     - sqrtf(fmaf(d2x, d2x, fmaf(d2y, d2y, EPS)));
            cost_out[0] = cost_in[0] + A_COST * dev + B_COST * blm - pg;
        }
    }
}

extern "C" void kernel_launch(void* const* d_in, const int* in_sizes, int n_in,
                              void* d_out, int out_size) {
    const float* state      = (const float*)d_in[0];
    const float* cost_in    = (const float*)d_in[1];
    const float* stacked_in = (const float*)d_in[2];
    const float* goal       = (const float*)d_in[3];
    const float* observed   = (const float*)d_in[4];

    float* out = (float*)d_out;
    float* out_state   = out;
    float* out_cost    = out + NPED*4;
    float* out_stacked = out + NPED*4 + 1;

    forces_prop_stack_kernel<<<NPED/8, 256>>>(state, goal, stacked_in,
                                              out_state, out_stacked);
    cost_kernel<<<1, 1024>>>(state, goal, observed, cost_in, out_state, out_cost);
}